// round 1
// baseline (speedup 1.0000x reference)
#include <cuda_runtime.h>
#include <cstdint>

#define N_ELEC 8192
#define N_NUC  512
#define EMB    256
#define KER    256
#define DF     64
#define MID    128
#define NEDGE  131072
#define TILE_E 64

typedef unsigned long long ull;

// Scratch (device globals: no allocations allowed)
__device__ float g_H[N_ELEC * KER];          // 8 MB: electrons @ h_w
__device__ float g_Z[(size_t)N_ELEC * 3 * KER]; // 24 MB: concat [z_same | z_anti | z_n]

// ---------------- packed f32x2 helpers ----------------
__device__ __forceinline__ ull pack2(float x, float y) {
    ull r; asm("mov.b64 %0, {%1, %2};" : "=l"(r) : "f"(x), "f"(y)); return r;
}
__device__ __forceinline__ void unpack2(ull v, float& x, float& y) {
    asm("mov.b64 {%0, %1}, %2;" : "=f"(x), "=f"(y) : "l"(v));
}
__device__ __forceinline__ void fma2(ull& acc, ull a, ull b) {
    asm("fma.rn.f32x2 %0, %1, %2, %0;" : "+l"(acc) : "l"(a), "l"(b));
}
__device__ __forceinline__ ull mul2(ull a, ull b) {
    ull r; asm("mul.rn.f32x2 %0, %1, %2;" : "=l"(r) : "l"(a), "l"(b)); return r;
}
__device__ __forceinline__ void red_add_v4(float* p, float x, float y, float z, float w) {
    asm volatile("red.global.add.v4.f32 [%0], {%1, %2, %3, %4};"
                 :: "l"(p), "f"(x), "f"(y), "f"(z), "f"(w) : "memory");
}
// shifted softplus: log(0.5*e^x + 0.5) = max(x,0) + log(1+e^-|x|) - ln2
__device__ __forceinline__ float ssp(float x) {
    float t = __expf(-fabsf(x));
    return fmaxf(x, 0.0f) + __logf(1.0f + t) - 0.6931471805599453f;
}

// ---------------- fused edge kernel ----------------
// Per 64-edge tile: mid = ssp(dist@w1+b1) [64x128]; we = mid@w2 [64x256];
// weh = we * src[senders]; red-add into Z[recv*768 + zofs + k].
// Weights resident in SMEM (persistent CTAs).
#define EDGE_SMEM_FLOATS (DF*MID + MID + MID*KER + TILE_E*DF + TILE_E*MID)

__global__ void __launch_bounds__(256, 1)
edge_kernel(const float* __restrict__ dist, const float* __restrict__ w1,
            const float* __restrict__ b1, const float* __restrict__ w2,
            const float* __restrict__ src, const int* __restrict__ senders,
            const int* __restrict__ receivers, float* __restrict__ Z, int zofs)
{
    extern __shared__ __align__(16) float sm[];
    float* w1s   = sm;                    // [64][128]
    float* b1s   = w1s + DF * MID;        // [128]
    float* w2s   = b1s + MID;             // [128][256]
    float* dists = w2s + MID * KER;       // [64][64]
    float* mids  = dists + TILE_E * DF;   // [64][128]

    const int tid = threadIdx.x;
    // stage weights into SMEM once
    for (int i = tid; i < DF * MID / 4; i += 256)
        ((float4*)w1s)[i] = ((const float4*)w1)[i];
    for (int i = tid; i < MID * KER / 4; i += 256)
        ((float4*)w2s)[i] = ((const float4*)w2)[i];
    if (tid < MID) b1s[tid] = b1[tid];
    __syncthreads();

    const int warp = tid >> 5, lane = tid & 31;
    const float4 b1v = *(const float4*)&b1s[lane * 4];

    for (int tile = blockIdx.x; tile < NEDGE / TILE_E; tile += gridDim.x) {
        // load dist tile (coalesced)
        const float4* dsrc = (const float4*)(dist + (size_t)tile * TILE_E * DF);
        for (int i = tid; i < TILE_E * DF / 4; i += 256)
            ((float4*)dists)[i] = dsrc[i];
        __syncthreads();

        // ---- stage 1: mid = ssp(dist @ w1 + b1) ----
        {
            ull acc[8][2];
            #pragma unroll
            for (int i = 0; i < 8; i++) { acc[i][0] = 0ull; acc[i][1] = 0ull; }
            const float* dbase = dists + (warp * 8) * DF;
            #pragma unroll 2
            for (int k = 0; k < DF; k++) {
                ulonglong2 bv = *(const ulonglong2*)&w1s[k * MID + lane * 4];
                #pragma unroll
                for (int i = 0; i < 8; i++) {
                    float a = dbase[i * DF + k];
                    ull a2 = pack2(a, a);
                    fma2(acc[i][0], a2, bv.x);
                    fma2(acc[i][1], a2, bv.y);
                }
            }
            #pragma unroll
            for (int i = 0; i < 8; i++) {
                float x0, x1, x2, x3;
                unpack2(acc[i][0], x0, x1);
                unpack2(acc[i][1], x2, x3);
                float4 v;
                v.x = ssp(x0 + b1v.x); v.y = ssp(x1 + b1v.y);
                v.z = ssp(x2 + b1v.z); v.w = ssp(x3 + b1v.w);
                *(float4*)&mids[(warp * 8 + i) * MID + lane * 4] = v;
            }
        }
        __syncthreads();

        // ---- stage 2: we = mid @ w2; gather, multiply, scatter ----
        {
            ull accA[8][2], accB[8][2];
            #pragma unroll
            for (int i = 0; i < 8; i++) {
                accA[i][0] = accA[i][1] = 0ull;
                accB[i][0] = accB[i][1] = 0ull;
            }
            const float* mbase = mids + (warp * 8) * MID;
            #pragma unroll 2
            for (int m = 0; m < MID; m++) {
                ulonglong2 bA = *(const ulonglong2*)&w2s[m * KER + lane * 4];
                ulonglong2 bB = *(const ulonglong2*)&w2s[m * KER + 128 + lane * 4];
                #pragma unroll
                for (int i = 0; i < 8; i++) {
                    float a = mbase[i * MID + m];
                    ull a2 = pack2(a, a);
                    fma2(accA[i][0], a2, bA.x);
                    fma2(accA[i][1], a2, bA.y);
                    fma2(accB[i][0], a2, bB.x);
                    fma2(accB[i][1], a2, bB.y);
                }
            }
            const int ebase = tile * TILE_E + warp * 8;
            #pragma unroll
            for (int i = 0; i < 8; i++) {
                int s = __ldg(&senders[ebase + i]);
                int r = __ldg(&receivers[ebase + i]);
                const float* hrow = src + (size_t)s * KER;
                ulonglong2 hA = *(const ulonglong2*)(hrow + lane * 4);
                ulonglong2 hB = *(const ulonglong2*)(hrow + 128 + lane * 4);
                ull wA0 = mul2(accA[i][0], hA.x);
                ull wA1 = mul2(accA[i][1], hA.y);
                ull wB0 = mul2(accB[i][0], hB.x);
                ull wB1 = mul2(accB[i][1], hB.y);
                float p0, p1, p2, p3;
                float* zrow = Z + (size_t)r * 768 + zofs;
                unpack2(wA0, p0, p1); unpack2(wA1, p2, p3);
                red_add_v4(zrow + lane * 4, p0, p1, p2, p3);
                unpack2(wB0, p0, p1); unpack2(wB1, p2, p3);
                red_add_v4(zrow + 128 + lane * 4, p0, p1, p2, p3);
            }
        }
        __syncthreads();
    }
}

// ---------------- SGEMM: C[M,256] = A[M,K] @ B + optional residual ----------------
// B rows come from up to three 256x256 matrices (B0 for k<256, B1 for k<512, B2 else).
__global__ void __launch_bounds__(256)
sgemm256(const float* __restrict__ A, int K,
         const float* __restrict__ B0, const float* __restrict__ B1,
         const float* __restrict__ B2,
         const float* __restrict__ resid, float* __restrict__ C)
{
    __shared__ __align__(16) float As[8][132];
    __shared__ __align__(16) float Bs[8][128];
    const int tid = threadIdx.x;
    const int n0 = blockIdx.x * 128;
    const int m0 = blockIdx.y * 128;
    const int tr = tid >> 4, tc = tid & 15;

    ull acc[8][4];
    #pragma unroll
    for (int r = 0; r < 8; r++)
        #pragma unroll
        for (int c = 0; c < 4; c++) acc[r][c] = 0ull;

    const int m_l = tid >> 1, kq = (tid & 1) * 4;
    const int bk = tid >> 5, bn = (tid & 31) * 4;

    for (int k0 = 0; k0 < K; k0 += 8) {
        float4 av = *(const float4*)&A[(size_t)(m0 + m_l) * K + k0 + kq];
        const float* Bp = (k0 < 256) ? B0 : ((k0 < 512) ? B1 : B2);
        float4 bv = *(const float4*)&Bp[(size_t)((k0 + bk) & 255) * 256 + n0 + bn];
        __syncthreads();
        As[kq + 0][m_l] = av.x; As[kq + 1][m_l] = av.y;
        As[kq + 2][m_l] = av.z; As[kq + 3][m_l] = av.w;
        *(float4*)&Bs[bk][bn] = bv;
        __syncthreads();
        #pragma unroll
        for (int kk = 0; kk < 8; kk++) {
            float4 a0 = *(const float4*)&As[kk][tr * 8];
            float4 a1 = *(const float4*)&As[kk][tr * 8 + 4];
            ulonglong2 bb0 = *(const ulonglong2*)&Bs[kk][tc * 8];
            ulonglong2 bb1 = *(const ulonglong2*)&Bs[kk][tc * 8 + 4];
            float a[8] = {a0.x, a0.y, a0.z, a0.w, a1.x, a1.y, a1.z, a1.w};
            #pragma unroll
            for (int r = 0; r < 8; r++) {
                ull ar = pack2(a[r], a[r]);
                fma2(acc[r][0], ar, bb0.x);
                fma2(acc[r][1], ar, bb0.y);
                fma2(acc[r][2], ar, bb1.x);
                fma2(acc[r][3], ar, bb1.y);
            }
        }
    }
    #pragma unroll
    for (int r = 0; r < 8; r++) {
        size_t off = (size_t)(m0 + tr * 8 + r) * 256 + n0 + tc * 8;
        float4 o0, o1;
        unpack2(acc[r][0], o0.x, o0.y); unpack2(acc[r][1], o0.z, o0.w);
        unpack2(acc[r][2], o1.x, o1.y); unpack2(acc[r][3], o1.z, o1.w);
        if (resid) {
            float4 r0 = *(const float4*)&resid[off];
            float4 r1 = *(const float4*)&resid[off + 4];
            o0.x += r0.x; o0.y += r0.y; o0.z += r0.z; o0.w += r0.w;
            o1.x += r1.x; o1.y += r1.y; o1.z += r1.z; o1.w += r1.w;
        }
        *(float4*)&C[off] = o0;
        *(float4*)&C[off + 4] = o1;
    }
}

// ---------------- launch ----------------
extern "C" void kernel_launch(void* const* d_in, const int* in_sizes, int n_in,
                              void* d_out, int out_size)
{
    // Identify inputs by element count; relative order within each size class is
    // identical between setup_inputs dict order and reference signature order.
    const float *electrons = nullptr, *nuclei = nullptr, *h_w = nullptr;
    const float *dist[3] = {0, 0, 0}, *w1[3] = {0, 0, 0}, *b1[3] = {0, 0, 0};
    const float *w2[3] = {0, 0, 0}, *g[3] = {0, 0, 0};
    const int* idx6[6] = {0, 0, 0, 0, 0, 0};
    int nd = 0, n1 = 0, nb = 0, n2 = 0, ng = 0, ni = 0;
    bool have_nuc = false;
    for (int i = 0; i < n_in; i++) {
        int s = in_sizes[i];
        const void* p = d_in[i];
        if (s == N_ELEC * EMB)        electrons = (const float*)p;
        else if (s == NEDGE * DF)     { if (nd < 3) dist[nd++] = (const float*)p; }
        else if (s == DF * MID)       { if (n1 < 3) w1[n1++] = (const float*)p; }
        else if (s == MID)            { if (nb < 3) b1[nb++] = (const float*)p; }
        else if (s == MID * KER)      { if (n2 < 3) w2[n2++] = (const float*)p; }
        else if (s == KER * EMB)      { if (ng < 3) g[ng++] = (const float*)p; else h_w = (const float*)p; }
        else if (s == NEDGE)          { // 131072: nuclei first, then 6 index arrays
            if (!have_nuc) { nuclei = (const float*)p; have_nuc = true; }
            else if (ni < 6) idx6[ni++] = (const int*)p;
        }
    }
    const int* senders[3]   = { idx6[0], idx6[1], idx6[2] };
    const int* receivers[3] = { idx6[3], idx6[4], idx6[5] };

    float *Hbuf = nullptr, *Zbuf = nullptr;
    cudaGetSymbolAddress((void**)&Hbuf, g_H);
    cudaGetSymbolAddress((void**)&Zbuf, g_Z);

    const size_t edge_smem = EDGE_SMEM_FLOATS * sizeof(float);
    cudaFuncSetAttribute(edge_kernel, cudaFuncAttributeMaxDynamicSharedMemorySize,
                         (int)edge_smem);

    cudaMemsetAsync(Zbuf, 0, sizeof(float) * (size_t)N_ELEC * 3 * KER, 0);

    dim3 ggrid(2, 64); // 256 cols / 128, 8192 rows / 128
    // H = electrons @ h_w
    sgemm256<<<ggrid, 256>>>(electrons, 256, h_w, h_w, h_w, nullptr, Hbuf);

    // edge kernels: zofs {0,256,512} <-> final-GEMM B {g_same, g_anti, g_n}
    edge_kernel<<<148, 256, edge_smem>>>(dist[0], w1[0], b1[0], w2[0], Hbuf,
                                         senders[0], receivers[0], Zbuf, 0);
    edge_kernel<<<148, 256, edge_smem>>>(dist[1], w1[1], b1[1], w2[1], Hbuf,
                                         senders[1], receivers[1], Zbuf, 256);
    edge_kernel<<<148, 256, edge_smem>>>(dist[2], w1[2], b1[2], w2[2], nuclei,
                                         senders[2], receivers[2], Zbuf, 512);

    // out = electrons + Zcat @ [g_same; g_anti; g_n]
    sgemm256<<<ggrid, 256>>>(Zbuf, 768, g[0], g[1], g[2], electrons, (float*)d_out);
}

// round 4
// speedup vs baseline: 1.6355x; 1.6355x over previous
#include <cuda_runtime.h>
#include <cuda_bf16.h>
#include <cstdint>

#define N_ELEC 8192
#define N_NUC  512
#define EMB    256
#define KER    256
#define DF     64
#define MID    128
#define NEDGE  131072
#define TILE_M 128
#define NTILES (NEDGE / TILE_M)

typedef unsigned long long ull;

// ---------------- device scratch (no allocations allowed) ----------------
__device__ float g_H[N_ELEC * KER];                 // electrons @ h_w
__device__ float g_Z[(size_t)N_ELEC * 3 * KER];     // [z_same | z_anti | z_n] per row
__device__ __nv_bfloat16 g_w1img[3][2][DF * MID];   // [type][hi/lo] row-major [k][n]
__device__ __nv_bfloat16 g_w2img[3][2][MID * KER];  // [type][hi/lo] row-major [k][n]

// ---------------- helpers ----------------
__device__ __forceinline__ uint32_t smem_u32(const void* p) {
    uint32_t a;
    asm("{ .reg .u64 t; cvta.to.shared.u64 t, %1; cvt.u32.u64 %0, t; }" : "=r"(a) : "l"(p));
    return a;
}
__device__ __forceinline__ void ldsm4(uint32_t (&r)[4], uint32_t addr) {
    asm volatile("ldmatrix.sync.aligned.m8n8.x4.shared.b16 {%0,%1,%2,%3}, [%4];"
                 : "=r"(r[0]), "=r"(r[1]), "=r"(r[2]), "=r"(r[3]) : "r"(addr));
}
__device__ __forceinline__ void ldsm4t(uint32_t (&r)[4], uint32_t addr) {
    asm volatile("ldmatrix.sync.aligned.m8n8.x4.trans.shared.b16 {%0,%1,%2,%3}, [%4];"
                 : "=r"(r[0]), "=r"(r[1]), "=r"(r[2]), "=r"(r[3]) : "r"(addr));
}
__device__ __forceinline__ void mma16816(float (&d)[4], const uint32_t (&a)[4],
                                         uint32_t b0, uint32_t b1) {
    asm volatile("mma.sync.aligned.m16n8k16.row.col.f32.bf16.bf16.f32 "
                 "{%0,%1,%2,%3},{%4,%5,%6,%7},{%8,%9},{%0,%1,%2,%3};"
                 : "+f"(d[0]), "+f"(d[1]), "+f"(d[2]), "+f"(d[3])
                 : "r"(a[0]), "r"(a[1]), "r"(a[2]), "r"(a[3]), "r"(b0), "r"(b1));
}
__device__ __forceinline__ void red_add_v4(float* p, float x, float y, float z, float w) {
    asm volatile("red.global.add.v4.f32 [%0], {%1, %2, %3, %4};"
                 :: "l"(p), "f"(x), "f"(y), "f"(z), "f"(w) : "memory");
}
__device__ __forceinline__ float ssp(float x) {
    float t = __expf(-fabsf(x));
    return fmaxf(x, 0.0f) + __logf(1.0f + t) - 0.6931471805599453f;
}
__device__ __forceinline__ uint32_t pkbf(__nv_bfloat16 a, __nv_bfloat16 b) {
    return (uint32_t)__bfloat16_as_ushort(a) | ((uint32_t)__bfloat16_as_ushort(b) << 16);
}

// ---------------- weight prep: bf16 hi/lo split, row-major [k][n] ----------------
__global__ void prep_kernel(const float* w1_0, const float* w1_1, const float* w1_2,
                            const float* w2_0, const float* w2_1, const float* w2_2) {
    const float* w1p[3] = {w1_0, w1_1, w1_2};
    const float* w2p[3] = {w2_0, w2_1, w2_2};
    for (int i = blockIdx.x * blockDim.x + threadIdx.x; i < 3 * DF * MID;
         i += gridDim.x * blockDim.x) {
        int t = i / (DF * MID), e = i % (DF * MID);
        float v = w1p[t][e];
        __nv_bfloat16 hi = __float2bfloat16(v);
        g_w1img[t][0][e] = hi;
        g_w1img[t][1][e] = __float2bfloat16(v - __bfloat162float(hi));
    }
    for (int i = blockIdx.x * blockDim.x + threadIdx.x; i < 3 * MID * KER;
         i += gridDim.x * blockDim.x) {
        int t = i / (MID * KER), e = i % (MID * KER);
        float v = w2p[t][e];
        __nv_bfloat16 hi = __float2bfloat16(v);
        g_w2img[t][0][e] = hi;
        g_w2img[t][1][e] = __float2bfloat16(v - __bfloat162float(hi));
    }
}

// ---------------- smem byte offsets (padded rows for conflict-free ldmatrix) ----
// b1: 512 B
// dist hi/lo: [128][64] stride 72 elems -> 18432 B each
// w1  hi/lo:  [64][128] stride 136 elems -> 17408 B each
// w2  hi/lo:  [128][256] stride 264 elems -> 67584 B each
#define SO_B1  0
#define SO_DH  512
#define SO_DL  (SO_DH + 18432)
#define SO_W1H (SO_DL + 18432)
#define SO_W1L (SO_W1H + 17408)
#define SO_W2H (SO_W1L + 17408)
#define SO_W2L (SO_W2H + 67584)
#define EDGE_SMEM (SO_W2L + 67584)      // 207360 B

struct EdgeParams {
    const float* dist[3];
    const float* b1[3];
    const float* src[3];
    const int*   snd[3];
    const int*   rcv[3];
    float*       Z;
};

// ---------------- fused edge kernel (mma.sync bf16 split) ----------------
__global__ void __launch_bounds__(256, 1) edge_mma(EdgeParams P)
{
    extern __shared__ __align__(16) char smem[];
    const uint32_t sb = smem_u32(smem);
    const int tid = threadIdx.x, wid = tid >> 5, l = tid & 31;
    const int type = blockIdx.x % 3, cta = blockIdx.x / 3;
    const int m0 = wid * 16;

    // ---- stage weights + bias (persistent) ----
    {
        const uint4* w1g = (const uint4*)&g_w1img[type][0][0];  // 2 splits x 1024 uint4
        for (int i = tid; i < 2048; i += 256) {
            int sp = i >> 10, idx = i & 1023;
            int row = idx >> 4, ch = idx & 15;
            *(uint4*)(smem + (sp ? SO_W1L : SO_W1H) + row * 272 + ch * 16) =
                w1g[sp * 1024 + idx];
        }
        const uint4* w2g = (const uint4*)&g_w2img[type][0][0];  // 2 splits x 4096 uint4
        for (int i = tid; i < 8192; i += 256) {
            int sp = i >> 12, idx = i & 4095;
            int row = idx >> 5, ch = idx & 31;
            *(uint4*)(smem + (sp ? SO_W2L : SO_W2H) + row * 528 + ch * 16) =
                w2g[sp * 4096 + idx];
        }
        if (tid < MID) ((float*)(smem + SO_B1))[tid] = P.b1[type][tid];
    }
    __syncthreads();

    const float* b1s = (const float*)(smem + SO_B1);
    // per-lane ldmatrix address bases
    const uint32_t lrow = (uint32_t)(l & 15), lcol = (uint32_t)((l >> 4) << 3);
    const uint32_t daH = sb + SO_DH + ((m0 + lrow) * 72 + lcol) * 2;
    const uint32_t daL = daH + (SO_DL - SO_DH);
    const uint32_t w1H = sb + SO_W1H + (lrow * 136 + lcol) * 2;
    const uint32_t w1L = w1H + (SO_W1L - SO_W1H);
    const uint32_t w2H = sb + SO_W2H + (lrow * 264 + lcol) * 2;
    const uint32_t w2L = w2H + (SO_W2L - SO_W2H);

    const float* src = P.src[type];
    const int* snd = P.snd[type];
    const int* rcv = P.rcv[type];
    float* Z = P.Z;
    const int zofs = type * 256;

    for (int tile = cta; tile < NTILES; tile += 148) {
        // ---- stage dist tile: split f32 -> bf16 hi/lo into padded smem ----
        const float4* dsrc = (const float4*)(P.dist[type] + (size_t)tile * TILE_M * DF);
        for (int i = tid; i < 2048; i += 256) {
            float4 v = dsrc[i];
            int row = i >> 4, c4 = (i & 15) << 2;
            __nv_bfloat16 h0 = __float2bfloat16(v.x), h1 = __float2bfloat16(v.y);
            __nv_bfloat16 h2 = __float2bfloat16(v.z), h3 = __float2bfloat16(v.w);
            uint32_t off = (uint32_t)(row * 72 + c4) * 2;
            *(uint2*)(smem + SO_DH + off) = make_uint2(pkbf(h0, h1), pkbf(h2, h3));
            *(uint2*)(smem + SO_DL + off) = make_uint2(
                pkbf(__float2bfloat16(v.x - __bfloat162float(h0)),
                     __float2bfloat16(v.y - __bfloat162float(h1))),
                pkbf(__float2bfloat16(v.z - __bfloat162float(h2)),
                     __float2bfloat16(v.w - __bfloat162float(h3))));
        }
        __syncthreads();

        // ---- stage1: mid_raw = dist @ w1 (3 split terms, K=64, N=128) ----
        uint32_t Ah[4][4], Al[4][4];
        #pragma unroll
        for (int kt = 0; kt < 4; kt++) {
            ldsm4(Ah[kt], daH + kt * 32);
            ldsm4(Al[kt], daL + kt * 32);
        }
        float acc1[16][4];
        #pragma unroll
        for (int j = 0; j < 16; j++)
            #pragma unroll
            for (int c = 0; c < 4; c++) acc1[j][c] = 0.0f;
        #pragma unroll
        for (int kt = 0; kt < 4; kt++) {
            #pragma unroll
            for (int np = 0; np < 8; np++) {
                uint32_t bh[4], bl[4];
                ldsm4t(bh, w1H + kt * 4352 + np * 32);
                ldsm4t(bl, w1L + kt * 4352 + np * 32);
                mma16816(acc1[2 * np],     Ah[kt], bh[0], bh[1]);
                mma16816(acc1[2 * np + 1], Ah[kt], bh[2], bh[3]);
                mma16816(acc1[2 * np],     Ah[kt], bl[0], bl[1]);
                mma16816(acc1[2 * np + 1], Ah[kt], bl[2], bl[3]);
                mma16816(acc1[2 * np],     Al[kt], bh[0], bh[1]);
                mma16816(acc1[2 * np + 1], Al[kt], bh[2], bh[3]);
            }
        }

        // ---- epilogue1: bias + ssp + bf16 split; C-frag -> A-frag (register only) ----
        uint32_t mAh[8][4], mAl[8][4];
        #pragma unroll
        for (int j = 0; j < 16; j++) {
            float2 bv = *(const float2*)&b1s[8 * j + 2 * (l & 3)];
            float v0 = ssp(acc1[j][0] + bv.x), v1 = ssp(acc1[j][1] + bv.y);
            float v2 = ssp(acc1[j][2] + bv.x), v3 = ssp(acc1[j][3] + bv.y);
            __nv_bfloat16 h0 = __float2bfloat16(v0), h1 = __float2bfloat16(v1);
            __nv_bfloat16 h2 = __float2bfloat16(v2), h3 = __float2bfloat16(v3);
            uint32_t ph01 = pkbf(h0, h1), ph23 = pkbf(h2, h3);
            uint32_t pl01 = pkbf(__float2bfloat16(v0 - __bfloat162float(h0)),
                                 __float2bfloat16(v1 - __bfloat162float(h1)));
            uint32_t pl23 = pkbf(__float2bfloat16(v2 - __bfloat162float(h2)),
                                 __float2bfloat16(v3 - __bfloat162float(h3)));
            int kt = j >> 1;
            if ((j & 1) == 0) {
                mAh[kt][0] = ph01; mAh[kt][1] = ph23;
                mAl[kt][0] = pl01; mAl[kt][1] = pl23;
            } else {
                mAh[kt][2] = ph01; mAh[kt][3] = ph23;
                mAl[kt][2] = pl01; mAl[kt][3] = pl23;
            }
        }

        // ---- stage2 + epilogue2, four 64-col quarters ----
        const int eidx = tile * TILE_M + m0 + (l >> 2) + ((l & 1) << 3);
        const int s  = __ldg(&snd[eidx]);
        const int rc = __ldg(&rcv[eidx]);
        const float* hrow = src + (size_t)s * KER;
        float* zrow = Z + (size_t)rc * 768 + zofs;

        #pragma unroll
        for (int qt = 0; qt < 4; qt++) {
            float acc2[8][4];
            #pragma unroll
            for (int j = 0; j < 8; j++)
                #pragma unroll
                for (int c = 0; c < 4; c++) acc2[j][c] = 0.0f;
            #pragma unroll
            for (int kt = 0; kt < 8; kt++) {
                #pragma unroll
                for (int np = 0; np < 4; np++) {
                    const uint32_t nb = (uint32_t)(qt * 64 + np * 16) * 2;
                    uint32_t bh[4], bl[4];
                    ldsm4t(bh, w2H + kt * 8448 + nb);
                    ldsm4t(bl, w2L + kt * 8448 + nb);
                    mma16816(acc2[2 * np],     mAh[kt], bh[0], bh[1]);
                    mma16816(acc2[2 * np + 1], mAh[kt], bh[2], bh[3]);
                    mma16816(acc2[2 * np],     mAh[kt], bl[0], bl[1]);
                    mma16816(acc2[2 * np + 1], mAh[kt], bl[2], bl[3]);
                    mma16816(acc2[2 * np],     mAl[kt], bh[0], bh[1]);
                    mma16816(acc2[2 * np + 1], mAl[kt], bh[2], bh[3]);
                }
            }
            // epilogue: shuffle pairs into 4-wide vectors, gather h, red-add to Z
            #pragma unroll
            for (int j = 0; j < 8; j++) {
                float x0 = __shfl_xor_sync(0xFFFFFFFFu, acc2[j][0], 1);
                float x1 = __shfl_xor_sync(0xFFFFFFFFu, acc2[j][1], 1);
                float x2 = __shfl_xor_sync(0xFFFFFFFFu, acc2[j][2], 1);
                float x3 = __shfl_xor_sync(0xFFFFFFFFu, acc2[j][3], 1);
                int colg = qt * 64 + 8 * j + ((l & 2) << 1);
                float w0, w1, w2, w3;
                if ((l & 1) == 0) { w0 = acc2[j][0]; w1 = acc2[j][1]; w2 = x0; w3 = x1; }
                else              { w0 = x2; w1 = x3; w2 = acc2[j][2]; w3 = acc2[j][3]; }
                float4 hv = *(const float4*)&hrow[colg];
                red_add_v4(&zrow[colg], w0 * hv.x, w1 * hv.y, w2 * hv.z, w3 * hv.w);
            }
        }
        __syncthreads();
    }
}

// ---------------- FFMA2 SGEMM (known-good from Round 1) ----------------
__device__ __forceinline__ ull pack2(float x, float y) {
    ull r; asm("mov.b64 %0, {%1, %2};" : "=l"(r) : "f"(x), "f"(y)); return r;
}
__device__ __forceinline__ void unpack2(ull v, float& x, float& y) {
    asm("mov.b64 {%0, %1}, %2;" : "=f"(x), "=f"(y) : "l"(v));
}
__device__ __forceinline__ void fma2(ull& acc, ull a, ull b) {
    asm("fma.rn.f32x2 %0, %1, %2, %0;" : "+l"(acc) : "l"(a), "l"(b));
}

__global__ void __launch_bounds__(256)
sgemm256(const float* __restrict__ A, int K,
         const float* __restrict__ B0, const float* __restrict__ B1,
         const float* __restrict__ B2,
         const float* __restrict__ resid, float* __restrict__ C)
{
    __shared__ __align__(16) float As[8][132];
    __shared__ __align__(16) float Bs[8][128];
    const int tid = threadIdx.x;
    const int n0 = blockIdx.x * 128;
    const int m0 = blockIdx.y * 128;
    const int tr = tid >> 4, tc = tid & 15;

    ull acc[8][4];
    #pragma unroll
    for (int r = 0; r < 8; r++)
        #pragma unroll
        for (int c = 0; c < 4; c++) acc[r][c] = 0ull;

    const int m_l = tid >> 1, kq = (tid & 1) * 4;
    const int bk = tid >> 5, bn = (tid & 31) * 4;

    for (int k0 = 0; k0 < K; k0 += 8) {
        float4 av = *(const float4*)&A[(size_t)(m0 + m_l) * K + k0 + kq];
        const float* Bp = (k0 < 256) ? B0 : ((k0 < 512) ? B1 : B2);
        float4 bv = *(const float4*)&Bp[(size_t)((k0 + bk) & 255) * 256 + n0 + bn];
        __syncthreads();
        As[kq + 0][m_l] = av.x; As[kq + 1][m_l] = av.y;
        As[kq + 2][m_l] = av.z; As[kq + 3][m_l] = av.w;
        *(float4*)&Bs[bk][bn] = bv;
        __syncthreads();
        #pragma unroll
        for (int kk = 0; kk < 8; kk++) {
            float4 a0 = *(const float4*)&As[kk][tr * 8];
            float4 a1 = *(const float4*)&As[kk][tr * 8 + 4];
            ulonglong2 bb0 = *(const ulonglong2*)&Bs[kk][tc * 8];
            ulonglong2 bb1 = *(const ulonglong2*)&Bs[kk][tc * 8 + 4];
            float a[8] = {a0.x, a0.y, a0.z, a0.w, a1.x, a1.y, a1.z, a1.w};
            #pragma unroll
            for (int r = 0; r < 8; r++) {
                ull ar = pack2(a[r], a[r]);
                fma2(acc[r][0], ar, bb0.x);
                fma2(acc[r][1], ar, bb0.y);
                fma2(acc[r][2], ar, bb1.x);
                fma2(acc[r][3], ar, bb1.y);
            }
        }
    }
    #pragma unroll
    for (int r = 0; r < 8; r++) {
        size_t off = (size_t)(m0 + tr * 8 + r) * 256 + n0 + tc * 8;
        float4 o0, o1;
        unpack2(acc[r][0], o0.x, o0.y); unpack2(acc[r][1], o0.z, o0.w);
        unpack2(acc[r][2], o1.x, o1.y); unpack2(acc[r][3], o1.z, o1.w);
        if (resid) {
            float4 r0 = *(const float4*)&resid[off];
            float4 r1 = *(const float4*)&resid[off + 4];
            o0.x += r0.x; o0.y += r0.y; o0.z += r0.z; o0.w += r0.w;
            o1.x += r1.x; o1.y += r1.y; o1.z += r1.z; o1.w += r1.w;
        }
        *(float4*)&C[off] = o0;
        *(float4*)&C[off + 4] = o1;
    }
}

// ---------------- launch ----------------
extern "C" void kernel_launch(void* const* d_in, const int* in_sizes, int n_in,
                              void* d_out, int out_size)
{
    const float *electrons = nullptr, *nuclei = nullptr, *h_w = nullptr;
    const float *dist[3] = {0, 0, 0}, *w1[3] = {0, 0, 0}, *b1[3] = {0, 0, 0};
    const float *w2[3] = {0, 0, 0}, *g[3] = {0, 0, 0};
    const int* idx6[6] = {0, 0, 0, 0, 0, 0};
    int nd = 0, n1 = 0, nb = 0, n2 = 0, ng = 0, ni = 0;
    bool have_nuc = false;
    for (int i = 0; i < n_in; i++) {
        int s = in_sizes[i];
        const void* p = d_in[i];
        if (s == N_ELEC * EMB)        electrons = (const float*)p;
        else if (s == NEDGE * DF)     { if (nd < 3) dist[nd++] = (const float*)p; }
        else if (s == DF * MID)       { if (n1 < 3) w1[n1++] = (const float*)p; }
        else if (s == MID)            { if (nb < 3) b1[nb++] = (const float*)p; }
        else if (s == MID * KER)      { if (n2 < 3) w2[n2++] = (const float*)p; }
        else if (s == KER * EMB)      { if (ng < 3) g[ng++] = (const float*)p; else h_w = (const float*)p; }
        else if (s == NEDGE)          {  // 131072: nuclei (512*256) first, then 6 index arrays
            if (!have_nuc) { nuclei = (const float*)p; have_nuc = true; }
            else if (ni < 6) idx6[ni++] = (const int*)p;
        }
    }

    float *Hbuf = nullptr, *Zbuf = nullptr;
    cudaGetSymbolAddress((void**)&Hbuf, g_H);
    cudaGetSymbolAddress((void**)&Zbuf, g_Z);

    cudaFuncSetAttribute(edge_mma, cudaFuncAttributeMaxDynamicSharedMemorySize, EDGE_SMEM);

    prep_kernel<<<128, 256>>>(w1[0], w1[1], w1[2], w2[0], w2[1], w2[2]);
    cudaMemsetAsync(Zbuf, 0, sizeof(float) * (size_t)N_ELEC * 3 * KER, 0);

    dim3 ggrid(2, 64);
    // H = electrons @ h_w
    sgemm256<<<ggrid, 256>>>(electrons, 256, h_w, h_w, h_w, nullptr, Hbuf);

    EdgeParams P;
    for (int t = 0; t < 3; t++) {
        P.dist[t] = dist[t];
        P.b1[t] = b1[t];
        P.snd[t] = idx6[t];
        P.rcv[t] = idx6[3 + t];
    }
    P.src[0] = Hbuf; P.src[1] = Hbuf; P.src[2] = nuclei;
    P.Z = Zbuf;
    edge_mma<<<444, 256, EDGE_SMEM>>>(P);

    // out = electrons + Zcat @ [g_same; g_anti; g_n]
    sgemm256<<<ggrid, 256>>>(Zbuf, 768, g[0], g[1], g[2], electrons, (float*)d_out);
}

// round 5
// speedup vs baseline: 1.7545x; 1.0727x over previous
#include <cuda_runtime.h>
#include <cuda_bf16.h>
#include <cstdint>

#define N_ELEC 8192
#define N_NUC  512
#define EMB    256
#define KER    256
#define DF     64
#define MID    128
#define NEDGE  131072
#define TILE_M 128
#define NTILES (NEDGE / TILE_M)

// ---------------- device scratch (no allocations allowed) ----------------
__device__ float g_H[N_ELEC * KER];                 // electrons @ h_w
__device__ float g_Z[(size_t)N_ELEC * 3 * KER];     // [z_same | z_anti | z_n] per row
__device__ __nv_bfloat16 g_w1img[3][2][DF * MID];   // [type][hi/lo] row-major [k][n]
__device__ __nv_bfloat16 g_w2img[3][2][MID * KER];  // [type][hi/lo] row-major [k][n]
__device__ __nv_bfloat16 g_hws[2][EMB * KER];       // h_w split  [k][n]
__device__ __nv_bfloat16 g_gcs[2][3 * KER * EMB];   // gcat split [k][n], rows: g0|g1|g2

// ---------------- helpers ----------------
__device__ __forceinline__ uint32_t smem_u32(const void* p) {
    uint32_t a;
    asm("{ .reg .u64 t; cvta.to.shared.u64 t, %1; cvt.u32.u64 %0, t; }" : "=r"(a) : "l"(p));
    return a;
}
__device__ __forceinline__ void ldsm4(uint32_t (&r)[4], uint32_t addr) {
    asm volatile("ldmatrix.sync.aligned.m8n8.x4.shared.b16 {%0,%1,%2,%3}, [%4];"
                 : "=r"(r[0]), "=r"(r[1]), "=r"(r[2]), "=r"(r[3]) : "r"(addr));
}
__device__ __forceinline__ void ldsm4t(uint32_t (&r)[4], uint32_t addr) {
    asm volatile("ldmatrix.sync.aligned.m8n8.x4.trans.shared.b16 {%0,%1,%2,%3}, [%4];"
                 : "=r"(r[0]), "=r"(r[1]), "=r"(r[2]), "=r"(r[3]) : "r"(addr));
}
__device__ __forceinline__ void mma16816(float (&d)[4], const uint32_t (&a)[4],
                                         uint32_t b0, uint32_t b1) {
    asm volatile("mma.sync.aligned.m16n8k16.row.col.f32.bf16.bf16.f32 "
                 "{%0,%1,%2,%3},{%4,%5,%6,%7},{%8,%9},{%0,%1,%2,%3};"
                 : "+f"(d[0]), "+f"(d[1]), "+f"(d[2]), "+f"(d[3])
                 : "r"(a[0]), "r"(a[1]), "r"(a[2]), "r"(a[3]), "r"(b0), "r"(b1));
}
__device__ __forceinline__ void red_add_v4(float* p, float x, float y, float z, float w) {
    asm volatile("red.global.add.v4.f32 [%0], {%1, %2, %3, %4};"
                 :: "l"(p), "f"(x), "f"(y), "f"(z), "f"(w) : "memory");
}
__device__ __forceinline__ float ssp(float x) {
    float t = __expf(-fabsf(x));
    return fmaxf(x, 0.0f) + __logf(1.0f + t) - 0.6931471805599453f;
}
__device__ __forceinline__ uint32_t pkbf(__nv_bfloat16 a, __nv_bfloat16 b) {
    return (uint32_t)__bfloat16_as_ushort(a) | ((uint32_t)__bfloat16_as_ushort(b) << 16);
}

// ---------------- weight prep: bf16 hi/lo split, row-major [k][n] ----------------
__global__ void prep_kernel(const float* w1_0, const float* w1_1, const float* w1_2,
                            const float* w2_0, const float* w2_1, const float* w2_2,
                            const float* hw, const float* g0, const float* g1,
                            const float* g2) {
    const float* w1p[3] = {w1_0, w1_1, w1_2};
    const float* w2p[3] = {w2_0, w2_1, w2_2};
    const int stride = gridDim.x * blockDim.x;
    const int t0 = blockIdx.x * blockDim.x + threadIdx.x;
    for (int i = t0; i < 3 * DF * MID; i += stride) {
        int t = i / (DF * MID), e = i % (DF * MID);
        float v = w1p[t][e];
        __nv_bfloat16 hi = __float2bfloat16(v);
        g_w1img[t][0][e] = hi;
        g_w1img[t][1][e] = __float2bfloat16(v - __bfloat162float(hi));
    }
    for (int i = t0; i < 3 * MID * KER; i += stride) {
        int t = i / (MID * KER), e = i % (MID * KER);
        float v = w2p[t][e];
        __nv_bfloat16 hi = __float2bfloat16(v);
        g_w2img[t][0][e] = hi;
        g_w2img[t][1][e] = __float2bfloat16(v - __bfloat162float(hi));
    }
    for (int i = t0; i < EMB * KER; i += stride) {
        float v = hw[i];
        __nv_bfloat16 hi = __float2bfloat16(v);
        g_hws[0][i] = hi;
        g_hws[1][i] = __float2bfloat16(v - __bfloat162float(hi));
    }
    for (int i = t0; i < 3 * KER * EMB; i += stride) {
        int t = i / (KER * EMB), e = i % (KER * EMB);
        float v = (t == 0 ? g0 : (t == 1 ? g1 : g2))[e];
        __nv_bfloat16 hi = __float2bfloat16(v);
        g_gcs[0][i] = hi;
        g_gcs[1][i] = __float2bfloat16(v - __bfloat162float(hi));
    }
}

// ---------------- smem byte offsets (padded rows for conflict-free ldmatrix) ----
#define SO_B1  0
#define SO_DH  512
#define SO_DL  (SO_DH + 18432)
#define SO_W1H (SO_DL + 18432)
#define SO_W1L (SO_W1H + 17408)
#define SO_W2H (SO_W1L + 17408)
#define SO_W2L (SO_W2H + 67584)
#define EDGE_SMEM (SO_W2L + 67584)      // 207360 B

struct EdgeParams {
    const float* dist[3];
    const float* b1[3];
    const float* src[3];
    const int*   snd[3];
    const int*   rcv[3];
    float*       Z;
};

// ---------------- fused edge kernel (mma.sync bf16 split, 512 threads) ----------
__global__ void __launch_bounds__(512, 1) edge_mma(EdgeParams P)
{
    extern __shared__ __align__(16) char smem[];
    const uint32_t sb = smem_u32(smem);
    const int tid = threadIdx.x, wid = tid >> 5, l = tid & 31;
    const int type = blockIdx.x % 3, cta = blockIdx.x / 3;
    const int rg = wid >> 1, nh = wid & 1;   // 8 row-groups x 2 N-halves

    // ---- stage weights + bias (persistent) ----
    {
        const uint4* w1g = (const uint4*)&g_w1img[type][0][0];
        for (int i = tid; i < 2048; i += 512) {
            int sp = i >> 10, idx = i & 1023;
            int row = idx >> 4, ch = idx & 15;
            *(uint4*)(smem + (sp ? SO_W1L : SO_W1H) + row * 272 + ch * 16) =
                w1g[sp * 1024 + idx];
        }
        const uint4* w2g = (const uint4*)&g_w2img[type][0][0];
        for (int i = tid; i < 8192; i += 512) {
            int sp = i >> 12, idx = i & 4095;
            int row = idx >> 5, ch = idx & 31;
            *(uint4*)(smem + (sp ? SO_W2L : SO_W2H) + row * 528 + ch * 16) =
                w2g[sp * 4096 + idx];
        }
        if (tid < MID) ((float*)(smem + SO_B1))[tid] = P.b1[type][tid];
    }
    __syncthreads();

    const float* b1s = (const float*)(smem + SO_B1);
    const uint32_t lrow = (uint32_t)(l & 15), lc8 = (uint32_t)((l >> 4) << 3);
    const uint32_t daH = sb + SO_DH + ((rg * 16 + lrow) * 72 + lc8) * 2;
    const uint32_t daL = daH + (SO_DL - SO_DH);
    const uint32_t w1H = sb + SO_W1H + (lrow * 136 + lc8) * 2;
    const uint32_t w1L = w1H + (SO_W1L - SO_W1H);
    const uint32_t w2H = sb + SO_W2H + (lrow * 264 + lc8) * 2;
    const uint32_t w2L = w2H + (SO_W2L - SO_W2H);

    const float* src = P.src[type];
    const int* snd = P.snd[type];
    const int* rcv = P.rcv[type];
    float* Z = P.Z;
    const int zofs = type * 256;

    for (int tile = cta; tile < NTILES; tile += 148) {
        // ---- stage dist tile: split f32 -> bf16 hi/lo into padded smem ----
        const float4* dsrc = (const float4*)(P.dist[type] + (size_t)tile * TILE_M * DF);
        for (int i = tid; i < 2048; i += 512) {
            float4 v = dsrc[i];
            int row = i >> 4, c4 = (i & 15) << 2;
            __nv_bfloat16 h0 = __float2bfloat16(v.x), h1 = __float2bfloat16(v.y);
            __nv_bfloat16 h2 = __float2bfloat16(v.z), h3 = __float2bfloat16(v.w);
            uint32_t off = (uint32_t)(row * 72 + c4) * 2;
            *(uint2*)(smem + SO_DH + off) = make_uint2(pkbf(h0, h1), pkbf(h2, h3));
            *(uint2*)(smem + SO_DL + off) = make_uint2(
                pkbf(__float2bfloat16(v.x - __bfloat162float(h0)),
                     __float2bfloat16(v.y - __bfloat162float(h1))),
                pkbf(__float2bfloat16(v.z - __bfloat162float(h2)),
                     __float2bfloat16(v.w - __bfloat162float(h3))));
        }
        __syncthreads();

        // ---- stage1 (duplicated per N-half partner): mid = ssp(dist@w1+b1), 2 passes
        uint32_t mAh[8][4], mAl[8][4];
        #pragma unroll
        for (int pass = 0; pass < 2; pass++) {
            float acc1[8][4];
            #pragma unroll
            for (int j = 0; j < 8; j++)
                #pragma unroll
                for (int c = 0; c < 4; c++) acc1[j][c] = 0.0f;
            #pragma unroll
            for (int kt = 0; kt < 4; kt++) {
                uint32_t Ah[4], Al[4];
                ldsm4(Ah, daH + kt * 32);
                ldsm4(Al, daL + kt * 32);
                #pragma unroll
                for (int nc = 0; nc < 4; nc++) {
                    const uint32_t nb = (uint32_t)(pass * 64 + nc * 16) * 2;
                    uint32_t bh[4], bl[4];
                    ldsm4t(bh, w1H + kt * 4352 + nb);
                    ldsm4t(bl, w1L + kt * 4352 + nb);
                    mma16816(acc1[2 * nc],     Ah, bh[0], bh[1]);
                    mma16816(acc1[2 * nc + 1], Ah, bh[2], bh[3]);
                    mma16816(acc1[2 * nc],     Ah, bl[0], bl[1]);
                    mma16816(acc1[2 * nc + 1], Ah, bl[2], bl[3]);
                    mma16816(acc1[2 * nc],     Al, bh[0], bh[1]);
                    mma16816(acc1[2 * nc + 1], Al, bh[2], bh[3]);
                }
            }
            // bias + ssp + split -> A-fragments (register-only)
            #pragma unroll
            for (int j = 0; j < 8; j++) {
                float2 bv = *(const float2*)&b1s[pass * 64 + 8 * j + 2 * (l & 3)];
                float v0 = ssp(acc1[j][0] + bv.x), v1 = ssp(acc1[j][1] + bv.y);
                float v2 = ssp(acc1[j][2] + bv.x), v3 = ssp(acc1[j][3] + bv.y);
                __nv_bfloat16 h0 = __float2bfloat16(v0), h1 = __float2bfloat16(v1);
                __nv_bfloat16 h2 = __float2bfloat16(v2), h3 = __float2bfloat16(v3);
                uint32_t ph01 = pkbf(h0, h1), ph23 = pkbf(h2, h3);
                uint32_t pl01 = pkbf(__float2bfloat16(v0 - __bfloat162float(h0)),
                                     __float2bfloat16(v1 - __bfloat162float(h1)));
                uint32_t pl23 = pkbf(__float2bfloat16(v2 - __bfloat162float(h2)),
                                     __float2bfloat16(v3 - __bfloat162float(h3)));
                const int kt = pass * 4 + (j >> 1);
                if ((j & 1) == 0) {
                    mAh[kt][0] = ph01; mAh[kt][1] = ph23;
                    mAl[kt][0] = pl01; mAl[kt][1] = pl23;
                } else {
                    mAh[kt][2] = ph01; mAh[kt][3] = ph23;
                    mAl[kt][2] = pl01; mAl[kt][3] = pl23;
                }
            }
        }

        // ---- stage2 + scatter: this warp's 128-col half, four 32-col chunks ----
        const int eidx = tile * TILE_M + rg * 16 + (l >> 2) + ((l & 1) << 3);
        const int s  = __ldg(&snd[eidx]);
        const int rc = __ldg(&rcv[eidx]);
        const float* hrow = src + (size_t)s * KER;
        float* zrow = Z + (size_t)rc * 768 + zofs;

        #pragma unroll
        for (int ct = 0; ct < 4; ct++) {
            const int colbase = nh * 128 + ct * 32;
            float acc2[4][4];
            #pragma unroll
            for (int j = 0; j < 4; j++)
                #pragma unroll
                for (int c = 0; c < 4; c++) acc2[j][c] = 0.0f;
            #pragma unroll
            for (int kt = 0; kt < 8; kt++) {
                #pragma unroll
                for (int nc = 0; nc < 2; nc++) {
                    const uint32_t nb = (uint32_t)(colbase + nc * 16) * 2;
                    uint32_t bh[4], bl[4];
                    ldsm4t(bh, w2H + kt * 8448 + nb);
                    ldsm4t(bl, w2L + kt * 8448 + nb);
                    mma16816(acc2[2 * nc],     mAh[kt], bh[0], bh[1]);
                    mma16816(acc2[2 * nc + 1], mAh[kt], bh[2], bh[3]);
                    mma16816(acc2[2 * nc],     mAh[kt], bl[0], bl[1]);
                    mma16816(acc2[2 * nc + 1], mAh[kt], bl[2], bl[3]);
                    mma16816(acc2[2 * nc],     mAl[kt], bh[0], bh[1]);
                    mma16816(acc2[2 * nc + 1], mAl[kt], bh[2], bh[3]);
                }
            }
            #pragma unroll
            for (int j = 0; j < 4; j++) {
                float x0 = __shfl_xor_sync(0xFFFFFFFFu, acc2[j][0], 1);
                float x1 = __shfl_xor_sync(0xFFFFFFFFu, acc2[j][1], 1);
                float x2 = __shfl_xor_sync(0xFFFFFFFFu, acc2[j][2], 1);
                float x3 = __shfl_xor_sync(0xFFFFFFFFu, acc2[j][3], 1);
                int colg = colbase + 8 * j + ((l & 2) << 1);
                float w0, w1, w2, w3;
                if ((l & 1) == 0) { w0 = acc2[j][0]; w1 = acc2[j][1]; w2 = x0; w3 = x1; }
                else              { w0 = x2; w1 = x3; w2 = acc2[j][2]; w3 = acc2[j][3]; }
                float4 hv = *(const float4*)&hrow[colg];
                red_add_v4(&zrow[colg], w0 * hv.x, w1 * hv.y, w2 * hv.z, w3 * hv.w);
            }
        }
        __syncthreads();   // dist region safe to overwrite next tile
    }
}

// ---------------- HMMA bf16-split GEMM: C[8192,256] = A[M,K]f32 @ B(+resid) ----
// B pre-split bf16 row-major [K][256]. CTA tile 128m x 128n, K chunks of 64.
#define GA_H 0
#define GA_L 18432
#define GB_H 36864
#define GB_L (36864 + 17408)
#define GEMM_SMEM (GB_L + 17408)   // 71680

__global__ void __launch_bounds__(256, 2)
gemm_mma(const float* __restrict__ A, int K,
         const __nv_bfloat16* __restrict__ Bh, const __nv_bfloat16* __restrict__ Bl,
         const float* __restrict__ resid, float* __restrict__ C)
{
    extern __shared__ __align__(16) char smem[];
    const uint32_t sb = smem_u32(smem);
    const int tid = threadIdx.x, wid = tid >> 5, l = tid & 31;
    const int n0 = blockIdx.x * 128;
    const int m0 = blockIdx.y * 128;
    const int rg = wid;   // 8 warps x 16 rows

    const uint32_t lrow = (uint32_t)(l & 15), lc8 = (uint32_t)((l >> 4) << 3);
    const uint32_t aAH = sb + GA_H + ((rg * 16 + lrow) * 72 + lc8) * 2;
    const uint32_t aAL = aAH + (GA_L - GA_H);
    const uint32_t aBH = sb + GB_H + (lrow * 136 + lc8) * 2;
    const uint32_t aBL = aBH + (GB_L - GB_H);

    float acc[16][4];
    #pragma unroll
    for (int j = 0; j < 16; j++)
        #pragma unroll
        for (int c = 0; c < 4; c++) acc[j][c] = 0.0f;

    for (int k0 = 0; k0 < K; k0 += 64) {
        // stage A chunk [128][64] f32 -> bf16 hi/lo (stride 72 elems)
        for (int i = tid; i < 2048; i += 256) {
            int row = i >> 4, c4 = (i & 15) << 2;
            float4 v = *(const float4*)&A[(size_t)(m0 + row) * K + k0 + c4];
            __nv_bfloat16 h0 = __float2bfloat16(v.x), h1 = __float2bfloat16(v.y);
            __nv_bfloat16 h2 = __float2bfloat16(v.z), h3 = __float2bfloat16(v.w);
            uint32_t off = (uint32_t)(row * 72 + c4) * 2;
            *(uint2*)(smem + GA_H + off) = make_uint2(pkbf(h0, h1), pkbf(h2, h3));
            *(uint2*)(smem + GA_L + off) = make_uint2(
                pkbf(__float2bfloat16(v.x - __bfloat162float(h0)),
                     __float2bfloat16(v.y - __bfloat162float(h1))),
                pkbf(__float2bfloat16(v.z - __bfloat162float(h2)),
                     __float2bfloat16(v.w - __bfloat162float(h3))));
        }
        // stage B chunk [64][128] bf16 (stride 136 elems)
        for (int i = tid; i < 2048; i += 256) {
            int r = i >> 5, cg = (i & 31);
            uint2 vh = *(const uint2*)&Bh[(size_t)(k0 + r) * 256 + n0 + cg * 4];
            uint2 vl = *(const uint2*)&Bl[(size_t)(k0 + r) * 256 + n0 + cg * 4];
            uint32_t off = (uint32_t)(r * 272 + cg * 8);
            *(uint2*)(smem + GB_H + off) = vh;
            *(uint2*)(smem + GB_L + off) = vl;
        }
        __syncthreads();
        #pragma unroll
        for (int kt = 0; kt < 4; kt++) {
            uint32_t Ah[4], Al[4];
            ldsm4(Ah, aAH + kt * 32);
            ldsm4(Al, aAL + kt * 32);
            #pragma unroll
            for (int nc = 0; nc < 8; nc++) {
                uint32_t bh[4], bl[4];
                ldsm4t(bh, aBH + kt * 4352 + nc * 32);
                ldsm4t(bl, aBL + kt * 4352 + nc * 32);
                mma16816(acc[2 * nc],     Ah, bh[0], bh[1]);
                mma16816(acc[2 * nc + 1], Ah, bh[2], bh[3]);
                mma16816(acc[2 * nc],     Ah, bl[0], bl[1]);
                mma16816(acc[2 * nc + 1], Ah, bl[2], bl[3]);
                mma16816(acc[2 * nc],     Al, bh[0], bh[1]);
                mma16816(acc[2 * nc + 1], Al, bh[2], bh[3]);
            }
        }
        __syncthreads();
    }

    // epilogue: resid + store (float2 per fragment half)
    const int row0 = m0 + rg * 16 + (l >> 2);
    const int colb = n0 + 2 * (l & 3);
    #pragma unroll
    for (int jn = 0; jn < 16; jn++) {
        const int col = colb + jn * 8;
        size_t o0 = (size_t)row0 * 256 + col;
        size_t o1 = (size_t)(row0 + 8) * 256 + col;
        float2 p0 = make_float2(acc[jn][0], acc[jn][1]);
        float2 p1 = make_float2(acc[jn][2], acc[jn][3]);
        if (resid) {
            float2 r0 = *(const float2*)&resid[o0];
            float2 r1 = *(const float2*)&resid[o1];
            p0.x += r0.x; p0.y += r0.y;
            p1.x += r1.x; p1.y += r1.y;
        }
        *(float2*)&C[o0] = p0;
        *(float2*)&C[o1] = p1;
    }
}

// ---------------- launch ----------------
extern "C" void kernel_launch(void* const* d_in, const int* in_sizes, int n_in,
                              void* d_out, int out_size)
{
    const float *electrons = nullptr, *nuclei = nullptr, *h_w = nullptr;
    const float *dist[3] = {0, 0, 0}, *w1[3] = {0, 0, 0}, *b1[3] = {0, 0, 0};
    const float *w2[3] = {0, 0, 0}, *g[3] = {0, 0, 0};
    const int* idx6[6] = {0, 0, 0, 0, 0, 0};
    int nd = 0, n1 = 0, nb = 0, n2 = 0, ng = 0, ni = 0;
    bool have_nuc = false;
    for (int i = 0; i < n_in; i++) {
        int s = in_sizes[i];
        const void* p = d_in[i];
        if (s == N_ELEC * EMB)        electrons = (const float*)p;
        else if (s == NEDGE * DF)     { if (nd < 3) dist[nd++] = (const float*)p; }
        else if (s == DF * MID)       { if (n1 < 3) w1[n1++] = (const float*)p; }
        else if (s == MID)            { if (nb < 3) b1[nb++] = (const float*)p; }
        else if (s == MID * KER)      { if (n2 < 3) w2[n2++] = (const float*)p; }
        else if (s == KER * EMB)      { if (ng < 3) g[ng++] = (const float*)p; else h_w = (const float*)p; }
        else if (s == NEDGE)          {  // 131072: nuclei (512*256) first, then 6 index arrays
            if (!have_nuc) { nuclei = (const float*)p; have_nuc = true; }
            else if (ni < 6) idx6[ni++] = (const int*)p;
        }
    }

    float *Hbuf = nullptr, *Zbuf = nullptr;
    cudaGetSymbolAddress((void**)&Hbuf, g_H);
    cudaGetSymbolAddress((void**)&Zbuf, g_Z);
    __nv_bfloat16 *hws = nullptr, *gcs = nullptr;
    cudaGetSymbolAddress((void**)&hws, g_hws);
    cudaGetSymbolAddress((void**)&gcs, g_gcs);

    cudaFuncSetAttribute(edge_mma, cudaFuncAttributeMaxDynamicSharedMemorySize, EDGE_SMEM);
    cudaFuncSetAttribute(gemm_mma, cudaFuncAttributeMaxDynamicSharedMemorySize, GEMM_SMEM);

    prep_kernel<<<256, 256>>>(w1[0], w1[1], w1[2], w2[0], w2[1], w2[2],
                              h_w, g[0], g[1], g[2]);
    cudaMemsetAsync(Zbuf, 0, sizeof(float) * (size_t)N_ELEC * 3 * KER, 0);

    dim3 ggrid(2, 64);
    // H = electrons @ h_w
    gemm_mma<<<ggrid, 256, GEMM_SMEM>>>(electrons, 256, hws, hws + EMB * KER,
                                        nullptr, Hbuf);

    EdgeParams P;
    for (int t = 0; t < 3; t++) {
        P.dist[t] = dist[t];
        P.b1[t] = b1[t];
        P.snd[t] = idx6[t];
        P.rcv[t] = idx6[3 + t];
    }
    P.src[0] = Hbuf; P.src[1] = Hbuf; P.src[2] = nuclei;
    P.Z = Zbuf;
    edge_mma<<<444, 512, EDGE_SMEM>>>(P);

    // out = electrons + Zcat @ [g_same; g_anti; g_n]
    gemm_mma<<<ggrid, 256, GEMM_SMEM>>>(Zbuf, 768, gcs, gcs + 3 * KER * EMB,
                                        electrons, (float*)d_out);
}